// round 5
// baseline (speedup 1.0000x reference)
#include <cuda_runtime.h>
#include <cuda_fp16.h>
#include <cstdint>

#define N_NODES 50000
#define N_EDGES 1600000
#define N_GRAPHS 2048
#define D 133
#define DP 136           // fp32 padded row (floats)
#define DPH 144          // fp16 padded row (halves) = 288B
#define EPSV 1e-5f
#define XS_STRIDE 140    // xs row stride (floats), bank-conflict-free A frags
#define SCAN_B 1024
#define SCAN_NB ((N_NODES + SCAN_B - 1) / SCAN_B)   // 49

// -------- scratch (static device globals; no runtime allocation) --------
__device__ __align__(16) __half g_A16[(size_t)N_NODES * DPH];  // gemm out, dinv-scaled, fp16
__device__ __align__(16) float  g_C[(size_t)N_NODES * DP];     // gather out / layer-2 input
__device__ __align__(16) float  g_P[(size_t)N_GRAPHS * DP];    // pool accumulator
__device__ float g_dinv[N_NODES];
__device__ int   g_cnt[N_NODES];
__device__ int   g_off[N_NODES + 1];
__device__ int   g_cursor[N_NODES];
__device__ int   g_csr[N_EDGES];
__device__ int   g_bsum[SCAN_NB];
__device__ int   g_cntg[N_GRAPHS];
__device__ float g_post1[3 * DP];    // bias | s | t   (zero-padded)
__device__ float g_post2[3 * DP];

// ------------------------------------------------------------------
__global__ void zero_fused_kernel() {
    int i = blockIdx.x * blockDim.x + threadIdx.x;
    if (i < N_GRAPHS * DP) g_P[i] = 0.0f;
    if (i < N_NODES)       g_cnt[i] = 0;
}

__global__ void count_deg_kernel(const int* __restrict__ ei) {
    int e = blockIdx.x * blockDim.x + threadIdx.x;
    if (e < N_EDGES) atomicAdd(&g_cnt[__ldg(&ei[N_EDGES + e])], 1);
}

__global__ void dinv_kernel() {
    int i = blockIdx.x * blockDim.x + threadIdx.x;
    if (i < N_NODES) g_dinv[i] = rsqrtf((float)(g_cnt[i] + 1));   // +1 self-loop
}

// ---- 3-kernel exclusive scan of g_cnt -> g_off ----
__global__ void scan1_kernel() {
    __shared__ int sh[SCAN_B];
    int t = threadIdx.x;
    int i = blockIdx.x * SCAN_B + t;
    int v = (i < N_NODES) ? g_cnt[i] : 0;
    sh[t] = v;
    __syncthreads();
#pragma unroll
    for (int d = 1; d < SCAN_B; d <<= 1) {
        int x = (t >= d) ? sh[t - d] : 0;
        __syncthreads();
        sh[t] += x;
        __syncthreads();
    }
    if (i < N_NODES) g_off[i] = sh[t] - v;           // exclusive, local
    if (t == SCAN_B - 1) g_bsum[blockIdx.x] = sh[t];
}

__global__ void scan2_kernel() {
    if (threadIdx.x == 0) {
        int acc = 0;
        for (int b = 0; b < SCAN_NB; b++) {
            int v = g_bsum[b];
            g_bsum[b] = acc;
            acc += v;
        }
    }
}

__global__ void scan3_kernel() {
    int i = blockIdx.x * blockDim.x + threadIdx.x;
    if (i < N_NODES) {
        int o = g_off[i] + g_bsum[i / SCAN_B];
        g_off[i] = o;
        g_cursor[i] = o;
    }
    if (i == 0) g_off[N_NODES] = N_EDGES;
}

__global__ void fill_csr_kernel(const int* __restrict__ ei) {
    int e = blockIdx.x * blockDim.x + threadIdx.x;
    if (e < N_EDGES) {
        int r = __ldg(&ei[e]);
        int c = __ldg(&ei[N_EDGES + e]);
        int pos = atomicAdd(&g_cursor[c], 1);
        g_csr[pos] = r;
    }
}

// ---- per-layer fused BN constants: bias | s | t, zero-padded to DP ----
__global__ void prep_post_kernel(const float* __restrict__ bias, const float* __restrict__ gam,
                                 const float* __restrict__ beta, const float* __restrict__ rm,
                                 const float* __restrict__ rv, float* __restrict__ dst) {
    int c = threadIdx.x;
    if (c >= DP) return;
    float bb = 0.0f, ss = 0.0f, tt = 0.0f;
    if (c < D) {
        bb = bias[c];
        float sc = gam[c] * rsqrtf(rv[c] + EPSV);
        ss = sc;
        tt = beta[c] - rm[c] * sc;
    }
    dst[c] = bb; dst[DP + c] = ss; dst[2 * DP + c] = tt;
}

// ------------------------------------------------------------------
__device__ __forceinline__ uint32_t f2tf32(float f) {
    uint32_t r;
    asm("cvt.rna.tf32.f32 %0, %1;" : "=r"(r) : "f"(f));
    return r;
}

__device__ __forceinline__ void mma_tf32(float* d,
                                         uint32_t a0, uint32_t a1, uint32_t a2, uint32_t a3,
                                         uint32_t b0, uint32_t b1) {
    asm volatile("mma.sync.aligned.m16n8k8.row.col.f32.tf32.tf32.f32 "
                 "{%0,%1,%2,%3}, {%4,%5,%6,%7}, {%8,%9}, {%0,%1,%2,%3};"
                 : "+f"(d[0]), "+f"(d[1]), "+f"(d[2]), "+f"(d[3])
                 : "r"(a0), "r"(a1), "r"(a2), "r"(a3), "r"(b0), "r"(b1));
}

// Tensor-core GEMM: g_A16[row] = fp16( dinv[row] * (X @ W) ), pads zeroed.
// 8 warps/block; each warp: 16 rows x 136 cols via 17 n-tiles of m16n8k8 tf32.
// W (tf32 bits) in smem [136][136]; X staged per-warp [16][XS_STRIDE].
__global__ __launch_bounds__(256)
void gemm_tc_kernel(const float* __restrict__ X, int ldx,
                    const float* __restrict__ W) {
    extern __shared__ uint32_t smu[];
    uint32_t* ws = smu;                      // [136*136] tf32 bits
    uint32_t* xs = smu + 136 * 136;          // [8 warps][16][XS_STRIDE]

    int tid  = threadIdx.x;
    int w    = tid >> 5;
    int lane = tid & 31;

    // zero W pads, then fill converted W
    for (int i = tid; i < 136 * 136; i += 256) ws[i] = 0u;
    __syncthreads();
    for (int i = tid; i < D * D; i += 256) {
        int k = i / D, n = i - k * D;
        ws[k * 136 + n] = f2tf32(W[i]);
    }

    // stage this warp's 16 X rows (tf32-converted, zero-padded)
    int rowbase = (blockIdx.x * 8 + w) * 16;
    uint32_t* xw = xs + w * 16 * XS_STRIDE;
    for (int r = 0; r < 16; r++) {
        int row = rowbase + r;
        const float* Xr = X + (size_t)row * ldx;
        for (int c = lane; c < 136; c += 32)
            xw[r * XS_STRIDE + c] = (row < N_NODES && c < D) ? f2tf32(Xr[c]) : 0u;
    }
    __syncthreads();

    float acc[17][4];
#pragma unroll
    for (int nt = 0; nt < 17; nt++)
#pragma unroll
        for (int q = 0; q < 4; q++) acc[nt][q] = 0.0f;

    const int r0 = lane >> 2;        // A-frag row group 0..7
    const int kc = lane & 3;         // A-frag k within quad
    const int bn = lane >> 2;        // B-frag n
    const int bk = lane & 3;         // B-frag k

    for (int ks = 0; ks < 17; ks++) {
        uint32_t a0 = xw[r0 * XS_STRIDE + ks * 8 + kc];
        uint32_t a1 = xw[(r0 + 8) * XS_STRIDE + ks * 8 + kc];
        uint32_t a2 = xw[r0 * XS_STRIDE + ks * 8 + kc + 4];
        uint32_t a3 = xw[(r0 + 8) * XS_STRIDE + ks * 8 + kc + 4];
        const uint32_t* wr0 = ws + (ks * 8 + bk) * 136 + bn;
        const uint32_t* wr1 = ws + (ks * 8 + bk + 4) * 136 + bn;
#pragma unroll
        for (int nt = 0; nt < 17; nt++) {
            uint32_t b0 = wr0[nt * 8];
            uint32_t b1 = wr1[nt * 8];
            mma_tf32(acc[nt], a0, a1, a2, a3, b0, b1);
        }
    }

    // epilogue: dinv scale -> fp16, half2 stores; D frag: rows (r0, r0+8), cols nt*8+2*kc+{0,1}
    int row0 = rowbase + r0;
    int row1 = row0 + 8;
    float dv0 = (row0 < N_NODES) ? g_dinv[row0] : 0.0f;
    float dv1 = (row1 < N_NODES) ? g_dinv[row1] : 0.0f;
    int cb = 2 * kc;
#pragma unroll
    for (int nt = 0; nt < 17; nt++) {
        int c = nt * 8 + cb;
        if (row0 < N_NODES)
            *(__half2*)(g_A16 + (size_t)row0 * DPH + c) =
                __floats2half2_rn(dv0 * acc[nt][0], dv0 * acc[nt][1]);
        if (row1 < N_NODES)
            *(__half2*)(g_A16 + (size_t)row1 * DPH + c) =
                __floats2half2_rn(dv1 * acc[nt][2], dv1 * acc[nt][3]);
    }
    if (kc == 0) {   // zero pads cols 136..143 (8 halves = 16B)
        if (row0 < N_NODES) *(uint4*)(g_A16 + (size_t)row0 * DPH + 136) = make_uint4(0, 0, 0, 0);
        if (row1 < N_NODES) *(uint4*)(g_A16 + (size_t)row1 * DPH + 136) = make_uint4(0, 0, 0, 0);
    }
}

// ------------------------------------------------------------------
// Warp-per-node CSR gather (fp16 messages, fp32 accum) + fused epilogue.
__global__ __launch_bounds__(256)
void gather_post_kernel(const __half* __restrict__ A, float* __restrict__ Cout,
                        const float* __restrict__ post, int do_pool,
                        const int* __restrict__ batch) {
    int gw = (blockIdx.x * blockDim.x + threadIdx.x) >> 5;
    if (gw >= N_NODES) return;
    int lane = threadIdx.x & 31;
    int n = gw;

    int lo = __ldg(&g_off[n]);
    int hi = __ldg(&g_off[n + 1]);

    float a[8];
#pragma unroll
    for (int i = 0; i < 8; i++) a[i] = 0.0f;

    if (lane < 17) {
        const uint4 v = __ldg((const uint4*)(A + (size_t)n * DPH) + lane);
        const __half2* h = (const __half2*)&v;
#pragma unroll
        for (int q = 0; q < 4; q++) {
            float2 f = __half22float2(h[q]);
            a[2 * q] += f.x; a[2 * q + 1] += f.y;
        }
    }

    int e = lo;
    for (; e + 32 <= hi; e += 32) {
        int src = __ldg(&g_csr[e + lane]);
#pragma unroll 4
        for (int j = 0; j < 32; j++) {
            int sj = __shfl_sync(0xffffffffu, src, j);
            if (lane < 17) {
                const uint4 v = __ldg((const uint4*)(A + (size_t)sj * DPH) + lane);
                const __half2* h = (const __half2*)&v;
#pragma unroll
                for (int q = 0; q < 4; q++) {
                    float2 f = __half22float2(h[q]);
                    a[2 * q] += f.x; a[2 * q + 1] += f.y;
                }
            }
        }
    }
    for (; e < hi; e++) {
        int sj = __ldg(&g_csr[e]);
        if (lane < 17) {
            const uint4 v = __ldg((const uint4*)(A + (size_t)sj * DPH) + lane);
            const __half2* h = (const __half2*)&v;
#pragma unroll
            for (int q = 0; q < 4; q++) {
                float2 f = __half22float2(h[q]);
                a[2 * q] += f.x; a[2 * q + 1] += f.y;
            }
        }
    }

    if (lane >= 17) return;

    float dv = __ldg(&g_dinv[n]);
    const float* bb = post;
    const float* ss = post + DP;
    const float* tt = post + 2 * DP;

    int c0 = 8 * lane;
    float o[8];
#pragma unroll
    for (int i = 0; i < 8; i++) {
        float v = fmaf(dv, a[i], __ldg(&bb[c0 + i]));
        o[i] = fmaf(fmaxf(v, 0.0f), __ldg(&ss[c0 + i]), __ldg(&tt[c0 + i]));
    }

    if (!do_pool) {
        float4* Cn = (float4*)(Cout + (size_t)n * DP + c0);
        Cn[0] = make_float4(o[0], o[1], o[2], o[3]);
        Cn[1] = make_float4(o[4], o[5], o[6], o[7]);
    } else {
        int g = __ldg(&batch[n]);
        float* dst = g_P + (size_t)g * DP + c0;
        unsigned long long p0 = (unsigned long long)__cvta_generic_to_global(dst);
        asm volatile("red.global.add.v4.f32 [%0], {%1,%2,%3,%4};"
                     :: "l"(p0), "f"(o[0]), "f"(o[1]), "f"(o[2]), "f"(o[3]) : "memory");
        unsigned long long p1 = (unsigned long long)__cvta_generic_to_global(dst + 4);
        asm volatile("red.global.add.v4.f32 [%0], {%1,%2,%3,%4};"
                     :: "l"(p1), "f"(o[4]), "f"(o[5]), "f"(o[6]), "f"(o[7]) : "memory");
    }
}

// ------------------------------------------------------------------
__device__ __forceinline__ int lbound(const int* b, int n, int v) {
    int lo = 0, hi = n;
    while (lo < hi) { int m = (lo + hi) >> 1; if (b[m] < v) lo = m + 1; else hi = m; }
    return lo;
}

__global__ void cntg_kernel(const int* __restrict__ batch) {
    int g = blockIdx.x * blockDim.x + threadIdx.x;
    if (g < N_GRAPHS)
        g_cntg[g] = lbound(batch, N_NODES, g + 1) - lbound(batch, N_NODES, g);
}

__global__ void divide_kernel(float* __restrict__ out) {
    int idx = blockIdx.x * blockDim.x + threadIdx.x;
    if (idx >= N_GRAPHS * D) return;
    int g = idx / D;
    int c = idx - g * D;
    float cnt = (float)g_cntg[g];
    out[idx] = g_P[(size_t)g * DP + c] / fmaxf(cnt, 1.0f);
}

// ------------------------------------------------------------------
extern "C" void kernel_launch(void* const* d_in, const int* in_sizes, int n_in,
                              void* d_out, int out_size) {
    const float* x     = (const float*)d_in[0];
    const int*   ei    = (const int*)d_in[1];
    const int*   batch = (const int*)d_in[2];
    const float* W1  = (const float*)d_in[3];
    const float* b1  = (const float*)d_in[4];
    const float* W2  = (const float*)d_in[5];
    const float* b2  = (const float*)d_in[6];
    const float* g1  = (const float*)d_in[7];
    const float* be1 = (const float*)d_in[8];
    const float* rm1 = (const float*)d_in[9];
    const float* rv1 = (const float*)d_in[10];
    const float* g2  = (const float*)d_in[11];
    const float* be2 = (const float*)d_in[12];
    const float* rm2 = (const float*)d_in[13];
    const float* rv2 = (const float*)d_in[14];
    float* out = (float*)d_out;

    __half* pA;
    float *pC, *pP1, *pP2;
    cudaGetSymbolAddress((void**)&pA, g_A16);
    cudaGetSymbolAddress((void**)&pC, g_C);
    cudaGetSymbolAddress((void**)&pP1, g_post1);
    cudaGetSymbolAddress((void**)&pP2, g_post2);

    const int smem = (136 * 136 + 8 * 16 * XS_STRIDE) * (int)sizeof(uint32_t);  // ~142 KB
    cudaFuncSetAttribute((const void*)gemm_tc_kernel,
                         cudaFuncAttributeMaxDynamicSharedMemorySize, smem);

    const int TB = 256;
    const int gemm_blocks   = (N_NODES + 128 - 1) / 128;          // 391
    const int gather_blocks = (N_NODES * 32 + TB - 1) / TB;       // warp per node

    // launch order puts gemm_tc at position #4 so ncu captures it
    zero_fused_kernel<<<(N_GRAPHS * DP + TB - 1) / TB, TB>>>();
    count_deg_kernel<<<(N_EDGES + TB - 1) / TB, TB>>>(ei);
    dinv_kernel<<<(N_NODES + TB - 1) / TB, TB>>>();

    // ---- layer 1 GEMM (#4) ----
    gemm_tc_kernel<<<gemm_blocks, TB, smem>>>(x, D, W1);

    // ---- CSR build (independent of gemm) ----
    scan1_kernel<<<SCAN_NB, SCAN_B>>>();
    scan2_kernel<<<1, 32>>>();
    scan3_kernel<<<SCAN_NB, SCAN_B>>>();
    fill_csr_kernel<<<(N_EDGES + TB - 1) / TB, TB>>>(ei);
    prep_post_kernel<<<1, DP>>>(b1, g1, be1, rm1, rv1, pP1);
    prep_post_kernel<<<1, DP>>>(b2, g2, be2, rm2, rv2, pP2);

    // ---- layer 1 gather ----
    gather_post_kernel<<<gather_blocks, TB>>>(pA, pC, pP1, 0, batch);

    // ---- layer 2 (+ fused pool accumulate) ----
    gemm_tc_kernel<<<gemm_blocks, TB, smem>>>(pC, DP, W2);
    gather_post_kernel<<<gather_blocks, TB>>>(pA, pC, pP2, 1, batch);

    // ---- per-graph mean ----
    cntg_kernel<<<(N_GRAPHS + TB - 1) / TB, TB>>>(batch);
    divide_kernel<<<(N_GRAPHS * D + TB - 1) / TB, TB>>>(out);
}

// round 6
// speedup vs baseline: 1.6533x; 1.6533x over previous
#include <cuda_runtime.h>
#include <cuda_fp16.h>
#include <cstdint>

#define N_NODES 50000
#define N_EDGES 1600000
#define N_GRAPHS 2048
#define D 133
#define DP 136           // fp32 padded row (floats)
#define DPH 144          // fp16 padded row (halves) = 288B
#define EPSV 1e-5f
#define SCAN_B 1024
#define SCAN_NB ((N_NODES + SCAN_B - 1) / SCAN_B)   // 49

// -------- scratch (static device globals; no runtime allocation) --------
__device__ __align__(16) __half g_A16[(size_t)N_NODES * DPH];  // gemm out, dinv-scaled, fp16
__device__ __align__(16) float  g_C[(size_t)N_NODES * DP];     // gather out / layer-2 input
__device__ __align__(16) float  g_P[(size_t)N_GRAPHS * DP];    // pool accumulator
__device__ float g_dinv[N_NODES];
__device__ int   g_cnt[N_NODES];
__device__ int   g_off[N_NODES + 1];
__device__ int   g_cursor[N_NODES];
__device__ int   g_csr[N_EDGES];
__device__ int   g_bsum[SCAN_NB];
__device__ int   g_cntg[N_GRAPHS];
__device__ float g_post1[3 * DP];    // bias | s | t   (zero-padded)
__device__ float g_post2[3 * DP];

// ------------------------------------------------------------------
__global__ void zero_fused_kernel() {
    int i = blockIdx.x * blockDim.x + threadIdx.x;
    if (i < N_GRAPHS * DP) g_P[i] = 0.0f;
    if (i < N_NODES)       g_cnt[i] = 0;
}

__global__ void count_deg_kernel(const int* __restrict__ ei) {
    int e = blockIdx.x * blockDim.x + threadIdx.x;
    if (e < N_EDGES) atomicAdd(&g_cnt[__ldg(&ei[N_EDGES + e])], 1);
}

__global__ void dinv_kernel() {
    int i = blockIdx.x * blockDim.x + threadIdx.x;
    if (i < N_NODES) g_dinv[i] = rsqrtf((float)(g_cnt[i] + 1));   // +1 self-loop
}

// ---- 3-kernel exclusive scan of g_cnt -> g_off ----
__global__ void scan1_kernel() {
    __shared__ int sh[SCAN_B];
    int t = threadIdx.x;
    int i = blockIdx.x * SCAN_B + t;
    int v = (i < N_NODES) ? g_cnt[i] : 0;
    sh[t] = v;
    __syncthreads();
#pragma unroll
    for (int d = 1; d < SCAN_B; d <<= 1) {
        int x = (t >= d) ? sh[t - d] : 0;
        __syncthreads();
        sh[t] += x;
        __syncthreads();
    }
    if (i < N_NODES) g_off[i] = sh[t] - v;           // exclusive, local
    if (t == SCAN_B - 1) g_bsum[blockIdx.x] = sh[t];
}

__global__ void scan2_kernel() {
    if (threadIdx.x == 0) {
        int acc = 0;
        for (int b = 0; b < SCAN_NB; b++) {
            int v = g_bsum[b];
            g_bsum[b] = acc;
            acc += v;
        }
    }
}

__global__ void scan3_kernel() {
    int i = blockIdx.x * blockDim.x + threadIdx.x;
    if (i < N_NODES) {
        int o = g_off[i] + g_bsum[i / SCAN_B];
        g_off[i] = o;
        g_cursor[i] = o;
    }
    if (i == 0) g_off[N_NODES] = N_EDGES;
}

__global__ void fill_csr_kernel(const int* __restrict__ ei) {
    int e = blockIdx.x * blockDim.x + threadIdx.x;
    if (e < N_EDGES) {
        int r = __ldg(&ei[e]);
        int c = __ldg(&ei[N_EDGES + e]);
        int pos = atomicAdd(&g_cursor[c], 1);
        g_csr[pos] = r;
    }
}

// ---- per-layer fused BN constants: bias | s | t, zero-padded to DP ----
__global__ void prep_post_kernel(const float* __restrict__ bias, const float* __restrict__ gam,
                                 const float* __restrict__ beta, const float* __restrict__ rm,
                                 const float* __restrict__ rv, float* __restrict__ dst) {
    int c = threadIdx.x;
    if (c >= DP) return;
    float bb = 0.0f, ss = 0.0f, tt = 0.0f;
    if (c < D) {
        bb = bias[c];
        float sc = gam[c] * rsqrtf(rv[c] + EPSV);
        ss = sc;
        tt = beta[c] - rm[c] * sc;
    }
    dst[c] = bb; dst[DP + c] = ss; dst[2 * DP + c] = tt;
}

// ------------------------------------------------------------------
__device__ __forceinline__ uint32_t f2tf32(float f) {
    uint32_t r;
    asm("cvt.rna.tf32.f32 %0, %1;" : "=r"(r) : "f"(f));
    return r;
}

__device__ __forceinline__ void mma_tf32(float* d,
                                         uint32_t a0, uint32_t a1, uint32_t a2, uint32_t a3,
                                         uint32_t b0, uint32_t b1) {
    asm volatile("mma.sync.aligned.m16n8k8.row.col.f32.tf32.tf32.f32 "
                 "{%0,%1,%2,%3}, {%4,%5,%6,%7}, {%8,%9}, {%0,%1,%2,%3};"
                 : "+f"(d[0]), "+f"(d[1]), "+f"(d[2]), "+f"(d[3])
                 : "r"(a0), "r"(a1), "r"(a2), "r"(a3), "r"(b0), "r"(b1));
}

// Tensor-core GEMM: g_A16[row] = fp16( dinv[row] * (X @ W) ), pads zeroed.
// smem = W only (74 KB tf32) -> 3 blocks/SM. A-frags loaded directly from
// global (each element consumed once). 8 warps x 16 rows = 128 rows/block.
__global__ __launch_bounds__(256)
void gemm_tc_kernel(const float* __restrict__ X, int ldx,
                    const float* __restrict__ W) {
    extern __shared__ uint32_t ws[];         // [136][136] tf32 bits, zero-padded

    int tid  = threadIdx.x;
    int w    = tid >> 5;
    int lane = tid & 31;

    // one-pass W fill (convert + zero-pad), unrolled for MLP
#pragma unroll 8
    for (int i = tid; i < 136 * 136; i += 256) {
        int k = i / 136, n = i - k * 136;
        ws[i] = (k < D && n < D) ? f2tf32(__ldg(&W[k * D + n])) : 0u;
    }
    __syncthreads();

    const int r0 = lane >> 2;        // A row group / B n
    const int kc = lane & 3;         // A k within quad / B k
    int rowbase = (blockIdx.x * 8 + w) * 16;
    int row0 = rowbase + r0;
    int row1 = row0 + 8;
    bool v0 = row0 < N_NODES;
    bool v1 = row1 < N_NODES;
    const float* X0 = X + (size_t)row0 * ldx;
    const float* X1 = X + (size_t)row1 * ldx;

    float acc[17][4];
#pragma unroll
    for (int nt = 0; nt < 17; nt++)
#pragma unroll
        for (int q = 0; q < 4; q++) acc[nt][q] = 0.0f;

#pragma unroll 4
    for (int ks = 0; ks < 17; ks++) {
        int c0 = ks * 8 + kc;
        int c1 = c0 + 4;
        uint32_t a0 = (v0 && c0 < D) ? f2tf32(__ldg(X0 + c0)) : 0u;
        uint32_t a1 = (v1 && c0 < D) ? f2tf32(__ldg(X1 + c0)) : 0u;
        uint32_t a2 = (v0 && c1 < D) ? f2tf32(__ldg(X0 + c1)) : 0u;
        uint32_t a3 = (v1 && c1 < D) ? f2tf32(__ldg(X1 + c1)) : 0u;
        const uint32_t* wr0 = ws + (ks * 8 + kc) * 136 + r0;   // bk=kc, bn=r0
        const uint32_t* wr1 = wr0 + 4 * 136;
#pragma unroll
        for (int nt = 0; nt < 17; nt++) {
            mma_tf32(acc[nt], a0, a1, a2, a3, wr0[nt * 8], wr1[nt * 8]);
        }
    }

    // epilogue: dinv scale -> fp16 half2 stores; D frag rows (r0, r0+8), cols nt*8+2*kc+{0,1}
    float dv0 = v0 ? g_dinv[row0] : 0.0f;
    float dv1 = v1 ? g_dinv[row1] : 0.0f;
    int cb = 2 * kc;
#pragma unroll
    for (int nt = 0; nt < 17; nt++) {
        int c = nt * 8 + cb;
        if (v0)
            *(__half2*)(g_A16 + (size_t)row0 * DPH + c) =
                __floats2half2_rn(dv0 * acc[nt][0], dv0 * acc[nt][1]);
        if (v1)
            *(__half2*)(g_A16 + (size_t)row1 * DPH + c) =
                __floats2half2_rn(dv1 * acc[nt][2], dv1 * acc[nt][3]);
    }
    if (kc == 0) {   // zero pads cols 136..143 (8 halves = 16B)
        if (v0) *(uint4*)(g_A16 + (size_t)row0 * DPH + 136) = make_uint4(0, 0, 0, 0);
        if (v1) *(uint4*)(g_A16 + (size_t)row1 * DPH + 136) = make_uint4(0, 0, 0, 0);
    }
}

// ------------------------------------------------------------------
// Warp-per-node CSR gather (fp16 messages, fp32 accum) + fused epilogue.
__global__ __launch_bounds__(256)
void gather_post_kernel(const __half* __restrict__ A, float* __restrict__ Cout,
                        const float* __restrict__ post, int do_pool,
                        const int* __restrict__ batch) {
    int gw = (blockIdx.x * blockDim.x + threadIdx.x) >> 5;
    if (gw >= N_NODES) return;
    int lane = threadIdx.x & 31;
    int n = gw;

    int lo = __ldg(&g_off[n]);
    int hi = __ldg(&g_off[n + 1]);

    float a[8];
#pragma unroll
    for (int i = 0; i < 8; i++) a[i] = 0.0f;

    if (lane < 17) {
        const uint4 v = __ldg((const uint4*)(A + (size_t)n * DPH) + lane);
        const __half2* h = (const __half2*)&v;
#pragma unroll
        for (int q = 0; q < 4; q++) {
            float2 f = __half22float2(h[q]);
            a[2 * q] += f.x; a[2 * q + 1] += f.y;
        }
    }

    int e = lo;
    for (; e + 32 <= hi; e += 32) {
        int src = __ldg(&g_csr[e + lane]);
#pragma unroll 4
        for (int j = 0; j < 32; j++) {
            int sj = __shfl_sync(0xffffffffu, src, j);
            if (lane < 17) {
                const uint4 v = __ldg((const uint4*)(A + (size_t)sj * DPH) + lane);
                const __half2* h = (const __half2*)&v;
#pragma unroll
                for (int q = 0; q < 4; q++) {
                    float2 f = __half22float2(h[q]);
                    a[2 * q] += f.x; a[2 * q + 1] += f.y;
                }
            }
        }
    }
    for (; e < hi; e++) {
        int sj = __ldg(&g_csr[e]);
        if (lane < 17) {
            const uint4 v = __ldg((const uint4*)(A + (size_t)sj * DPH) + lane);
            const __half2* h = (const __half2*)&v;
#pragma unroll
            for (int q = 0; q < 4; q++) {
                float2 f = __half22float2(h[q]);
                a[2 * q] += f.x; a[2 * q + 1] += f.y;
            }
        }
    }

    if (lane >= 17) return;

    float dv = __ldg(&g_dinv[n]);
    const float* bb = post;
    const float* ss = post + DP;
    const float* tt = post + 2 * DP;

    int c0 = 8 * lane;
    float o[8];
#pragma unroll
    for (int i = 0; i < 8; i++) {
        float v = fmaf(dv, a[i], __ldg(&bb[c0 + i]));
        o[i] = fmaf(fmaxf(v, 0.0f), __ldg(&ss[c0 + i]), __ldg(&tt[c0 + i]));
    }

    if (!do_pool) {
        float4* Cn = (float4*)(Cout + (size_t)n * DP + c0);
        Cn[0] = make_float4(o[0], o[1], o[2], o[3]);
        Cn[1] = make_float4(o[4], o[5], o[6], o[7]);
    } else {
        int g = __ldg(&batch[n]);
        float* dst = g_P + (size_t)g * DP + c0;
        unsigned long long p0 = (unsigned long long)__cvta_generic_to_global(dst);
        asm volatile("red.global.add.v4.f32 [%0], {%1,%2,%3,%4};"
                     :: "l"(p0), "f"(o[0]), "f"(o[1]), "f"(o[2]), "f"(o[3]) : "memory");
        unsigned long long p1 = (unsigned long long)__cvta_generic_to_global(dst + 4);
        asm volatile("red.global.add.v4.f32 [%0], {%1,%2,%3,%4};"
                     :: "l"(p1), "f"(o[4]), "f"(o[5]), "f"(o[6]), "f"(o[7]) : "memory");
    }
}

// ------------------------------------------------------------------
__device__ __forceinline__ int lbound(const int* b, int n, int v) {
    int lo = 0, hi = n;
    while (lo < hi) { int m = (lo + hi) >> 1; if (b[m] < v) lo = m + 1; else hi = m; }
    return lo;
}

__global__ void cntg_kernel(const int* __restrict__ batch) {
    int g = blockIdx.x * blockDim.x + threadIdx.x;
    if (g < N_GRAPHS)
        g_cntg[g] = lbound(batch, N_NODES, g + 1) - lbound(batch, N_NODES, g);
}

__global__ void divide_kernel(float* __restrict__ out) {
    int idx = blockIdx.x * blockDim.x + threadIdx.x;
    if (idx >= N_GRAPHS * D) return;
    int g = idx / D;
    int c = idx - g * D;
    float cnt = (float)g_cntg[g];
    out[idx] = g_P[(size_t)g * DP + c] / fmaxf(cnt, 1.0f);
}

// ------------------------------------------------------------------
extern "C" void kernel_launch(void* const* d_in, const int* in_sizes, int n_in,
                              void* d_out, int out_size) {
    const float* x     = (const float*)d_in[0];
    const int*   ei    = (const int*)d_in[1];
    const int*   batch = (const int*)d_in[2];
    const float* W1  = (const float*)d_in[3];
    const float* b1  = (const float*)d_in[4];
    const float* W2  = (const float*)d_in[5];
    const float* b2  = (const float*)d_in[6];
    const float* g1  = (const float*)d_in[7];
    const float* be1 = (const float*)d_in[8];
    const float* rm1 = (const float*)d_in[9];
    const float* rv1 = (const float*)d_in[10];
    const float* g2  = (const float*)d_in[11];
    const float* be2 = (const float*)d_in[12];
    const float* rm2 = (const float*)d_in[13];
    const float* rv2 = (const float*)d_in[14];
    float* out = (float*)d_out;

    __half* pA;
    float *pC, *pP1, *pP2;
    cudaGetSymbolAddress((void**)&pA, g_A16);
    cudaGetSymbolAddress((void**)&pC, g_C);
    cudaGetSymbolAddress((void**)&pP1, g_post1);
    cudaGetSymbolAddress((void**)&pP2, g_post2);

    const int smem = 136 * 136 * (int)sizeof(uint32_t);          // 74 KB -> 3 blocks/SM
    cudaFuncSetAttribute((const void*)gemm_tc_kernel,
                         cudaFuncAttributeMaxDynamicSharedMemorySize, smem);

    const int TB = 256;
    const int gemm_blocks   = (N_NODES + 128 - 1) / 128;          // 391
    const int gather_blocks = (N_NODES * 32 + TB - 1) / TB;       // warp per node

    // launch order puts gemm_tc at position #4 so ncu captures it
    zero_fused_kernel<<<(N_GRAPHS * DP + TB - 1) / TB, TB>>>();
    count_deg_kernel<<<(N_EDGES + TB - 1) / TB, TB>>>(ei);
    dinv_kernel<<<(N_NODES + TB - 1) / TB, TB>>>();

    // ---- layer 1 GEMM (#4) ----
    gemm_tc_kernel<<<gemm_blocks, TB, smem>>>(x, D, W1);

    // ---- CSR build (independent of gemm) ----
    scan1_kernel<<<SCAN_NB, SCAN_B>>>();
    scan2_kernel<<<1, 32>>>();
    scan3_kernel<<<SCAN_NB, SCAN_B>>>();
    fill_csr_kernel<<<(N_EDGES + TB - 1) / TB, TB>>>(ei);
    prep_post_kernel<<<1, DP>>>(b1, g1, be1, rm1, rv1, pP1);
    prep_post_kernel<<<1, DP>>>(b2, g2, be2, rm2, rv2, pP2);

    // ---- layer 1 gather ----
    gather_post_kernel<<<gather_blocks, TB>>>(pA, pC, pP1, 0, batch);

    // ---- layer 2 (+ fused pool accumulate) ----
    gemm_tc_kernel<<<gemm_blocks, TB, smem>>>(pC, DP, W2);
    gather_post_kernel<<<gather_blocks, TB>>>(pA, pC, pP2, 1, batch);

    // ---- per-graph mean ----
    cntg_kernel<<<(N_GRAPHS + TB - 1) / TB, TB>>>(batch);
    divide_kernel<<<(N_GRAPHS * D + TB - 1) / TB, TB>>>(out);
}